// round 11
// baseline (speedup 1.0000x reference)
#include <cuda_runtime.h>
#include <math.h>

#define BATCH 2
#define NCLS  34
#define HH    512
#define WW    1024
#define HWSZ  (HH*WW)          // 524288 = 2^19
#define TOPK  200
#define RAD   5

#define OFF_INST    0
#define OFF_SEG     (BATCH*HWSZ)
#define OFF_CENTERS (2*BATCH*HWSZ)
#define OFF_TOPV    (OFF_CENTERS + BATCH*TOPK*2)
#define OFF_ICLS    (OFF_TOPV + BATCH*TOPK)
#define OFF_IPROB   (OFF_ICLS + BATCH*TOPK)
#define OFF_ISZ     (OFF_IPROB + BATCH*TOPK)
#define OFF_CMAP    (OFF_ISZ + BATCH*TOPK)

__device__ float              g_vote[BATCH*HWSZ];
__device__ unsigned long long g_cand[BATCH][HWSZ];
__device__ int                g_cand_cnt[BATCH];
__device__ float              g_cx[BATCH][TOPK];
__device__ float              g_cy[BATCH][TOPK];
__device__ unsigned int       g_tpix[BATCH*HWSZ];
__device__ unsigned char      g_tcls[BATCH*HWSZ];
__device__ float              g_tprob[10][BATCH*HWSZ];
__device__ int                g_tcnt;
__device__ unsigned int       g_counts[BATCH*TOPK*10];
__device__ float              g_psum10[BATCH*TOPK*10];
__device__ unsigned int       g_done2[BATCH];

typedef unsigned long long ull;

__device__ __forceinline__ float f_inf()  { return __int_as_float(0x7f800000); }
__device__ __forceinline__ float f_ninf() { return __int_as_float(0xff800000); }

__device__ __forceinline__ ull pk2(float a, float b) {
    ull r; asm("mov.b64 %0, {%1,%2};" : "=l"(r) : "f"(a), "f"(b)); return r;
}
__device__ __forceinline__ void upk2(ull v, float& a, float& b) {
    asm("mov.b64 {%0,%1}, %2;" : "=f"(a), "=f"(b) : "l"(v));
}
__device__ __forceinline__ ull addf2(ull a, ull b) {
    ull r; asm("add.rn.f32x2 %0, %1, %2;" : "=l"(r) : "l"(a), "l"(b)); return r;
}
__device__ __forceinline__ ull mulf2(ull a, ull b) {
    ull r; asm("mul.rn.f32x2 %0, %1, %2;" : "=l"(r) : "l"(a), "l"(b)); return r;
}

// ---------------- K0: reset ----------------
__global__ void k0_reset() {
    int t = threadIdx.x;
    if (t < BATCH) { g_cand_cnt[t] = 0; g_done2[t] = 0; }
    if (t == 2) g_tcnt = 0;
    for (int i = t; i < BATCH*TOPK*10; i += blockDim.x) { g_counts[i] = 0; g_psum10[i] = 0.0f; }
}

// ---------------- K1: vote map (bit-exact, f32x2, 2 px/thread) ----------------
__global__ void k1_vote(const float* __restrict__ reg) {
    __shared__ float snx[18][76];
    __shared__ float sny[18][76];
    const int b  = blockIdx.z;
    const int bx = blockIdx.x * 64, by = blockIdx.y * 8;
    const int tid = threadIdx.y * 32 + threadIdx.x;
    const float* rxp = reg + (size_t)b * 2 * HWSZ;
    const float* ryp = rxp + HWSZ;
    for (int i = tid; i < 18*74; i += 256) {
        int sy = i / 74, sx = i % 74;
        int gy = by + sy - RAD, gx = bx + sx - RAD;
        float vx = 0.f, vy = 0.f;
        if (gy >= 0 && gy < HH && gx >= 0 && gx < WW) {
            int p = gy * WW + gx;
            vx = rxp[p]; vy = ryp[p];
        }
        snx[sy][sx] = -vx;
        sny[sy][sx] = -vy;
    }
    __syncthreads();
    const int tx = threadIdx.x, ty = threadIdx.y;
    const int cb = 2 * tx;
    ull acc = pk2(0.0f, 0.0f);
    #pragma unroll
    for (int i = 0; i < 11; i++) {
        #pragma unroll
        for (int j = 0; j < 11; j++) {
            const int dy = i - 5, dx = j - 5;
            if (dx*dx + dy*dy <= 25) {
                float nx0 = snx[ty + i][cb + j];
                float nx1 = snx[ty + i][cb + j + 1];
                float ny0 = sny[ty + i][cb + j];
                float ny1 = sny[ty + i][cb + j + 1];
                ull ox2 = pk2((float)dx, (float)dx);
                ull oy2 = pk2((float)dy, (float)dy);
                ull ddx = addf2(ox2, pk2(nx0, nx1));
                ull ddy = addf2(oy2, pk2(ny0, ny1));
                ull d2  = addf2(mulf2(ddx, ddx), mulf2(ddy, ddy));
                float lo, hi; upk2(d2, lo, hi);
                float s0 = __fsqrt_rn(lo);
                float s1 = __fsqrt_rn(hi);
                acc = addf2(acc, pk2(s0, s1));
            }
        }
    }
    float a0, a1; upk2(acc, a0, a1);
    float q0 = __fdiv_rn(a0, 81.0f);
    float q1 = __fdiv_rn(a1, 81.0f);
    float v0 = __fadd_rn(-q0, -1.0f);
    float v1 = __fadd_rn(-q1, -1.0f);
    int idx = ((int)b << 19) + (by + ty) * WW + bx + cb;
    *reinterpret_cast<float2*>(&g_vote[idx]) = make_float2(v0, v1);
}

// ---------------- K2: NMS (32x32 tile, 1024 thr) + per-batch last-block top-K ----------------
__global__ void k2_nms(float* __restrict__ out, float negthr) {
    __shared__ float sv[38][40];
    __shared__ float rm[38][32];
    __shared__ unsigned hist[256];
    __shared__ unsigned warpsum[8];
    __shared__ ull sk[512];
    __shared__ int sfill[TOPK];
    __shared__ int scnt;
    __shared__ unsigned s_prefix;
    __shared__ int s_target;
    __shared__ bool s_last;

    const int b  = blockIdx.z;
    const int bx = blockIdx.x * 32, by = blockIdx.y * 32;
    const int tid = threadIdx.y * 32 + threadIdx.x;
    for (int i = tid; i < 38*38; i += 1024) {
        int sy = i / 38, sx = i % 38;
        int gy = by + sy - 3, gx = bx + sx - 3;
        float v = f_ninf();
        if (gy >= 0 && gy < HH && gx >= 0 && gx < WW)
            v = g_vote[((int)b << 19) + gy * WW + gx];
        sv[sy][sx] = v;
    }
    __syncthreads();
    for (int i = tid; i < 38*32; i += 1024) {
        int sy = i >> 5, sx = i & 31;
        float m = sv[sy][sx];
        #pragma unroll
        for (int d = 1; d < 7; d++) m = fmaxf(m, sv[sy][sx + d]);
        rm[sy][sx] = m;
    }
    __syncthreads();
    const int tx = threadIdx.x, ty = threadIdx.y;
    {
        float v = sv[ty + 3][tx + 3];
        float p = rm[ty][tx];
        #pragma unroll
        for (int d = 1; d < 7; d++) p = fmaxf(p, rm[ty + d][tx]);
        bool keep = (p == v) && (v > negthr);
        int pix = (by + ty) * WW + (bx + tx);
        out[OFF_CMAP + ((int)b << 19) + pix] = keep ? v : 0.0f;
        if (keep) {
            unsigned bo = __float_as_uint(v);
            unsigned ob = ((int)bo < 0) ? ~bo : (bo ^ 0x80000000u);
            ull key = ((ull)(~ob) << 32) | (unsigned)pix;
            int pos = atomicAdd(&g_cand_cnt[b], 1);
            g_cand[b][pos] = key;
        }
    }
    // per-batch last block runs top-K for its batch (full 1024 threads)
    __threadfence();
    __syncthreads();
    if (tid == 0)
        s_last = (atomicAdd(&g_done2[b], 1u) == gridDim.x * gridDim.y - 1);
    __syncthreads();
    if (!s_last) return;

    const int n = (int)__ldcg((const int*)&g_cand_cnt[b]);
    unsigned kth = 0xFFFFFFFFu;
    if (n > TOPK) {
        unsigned prefix = 0; int target = TOPK;
        #pragma unroll
        for (int shift = 24; shift >= 0; shift -= 8) {
            if (tid < 256) hist[tid] = 0;
            __syncthreads();
            unsigned pm = (shift == 24) ? 0u : (0xFFFFFFFFu << (shift + 8));
            for (int i = tid; i < n; i += 1024) {
                unsigned kv = (unsigned)(__ldcg(&g_cand[b][i]) >> 32);
                if ((kv & pm) == prefix) atomicAdd(&hist[(kv >> shift) & 255u], 1u);
            }
            __syncthreads();
            unsigned h = 0, incl = 0;
            if (tid < 256) {
                h = hist[tid];
                incl = h;
                #pragma unroll
                for (int o = 1; o < 32; o <<= 1) {
                    unsigned t = __shfl_up_sync(0xFFFFFFFFu, incl, o);
                    if ((tid & 31) >= o) incl += t;
                }
                if ((tid & 31) == 31) warpsum[tid >> 5] = incl;
            }
            __syncthreads();
            if (tid < 8) {
                unsigned v = warpsum[tid];
                #pragma unroll
                for (int o = 1; o < 8; o <<= 1) {
                    unsigned t = __shfl_up_sync(0xFFu, v, o);
                    if (tid >= o) v += t;
                }
                warpsum[tid] = v;
            }
            __syncthreads();
            if (tid < 256) {
                unsigned tot = incl + ((tid >= 32) ? warpsum[(tid >> 5) - 1] : 0u);
                unsigned excl = tot - h;
                if ((int)excl < target && (int)tot >= target) {
                    s_prefix = prefix | ((unsigned)tid << shift);
                    s_target = target - (int)excl;
                }
            }
            __syncthreads();
            prefix = s_prefix; target = s_target;
            __syncthreads();
        }
        kth = prefix;
    }
    if (tid == 0) scnt = 0;
    __syncthreads();
    for (int i = tid; i < n; i += 1024) {
        ull key = __ldcg(&g_cand[b][i]);
        if ((unsigned)(key >> 32) <= kth) {
            int pos = atomicAdd(&scnt, 1);
            if (pos < 512) sk[pos] = key;
        }
    }
    __syncthreads();
    int m = scnt; if (m > 512) m = 512;
    for (int i = tid; i < 512; i += 1024) if (i >= m) sk[i] = 0xFFFFFFFFFFFFFFFFull;
    __syncthreads();
    for (int k = 2; k <= 512; k <<= 1) {
        for (int j = k >> 1; j > 0; j >>= 1) {
            if (tid < 512) {
                int i = tid, l = i ^ j;
                if (l > i) {
                    bool up = ((i & k) == 0);
                    ull a = sk[i], c = sk[l];
                    if ((a > c) == up) { sk[i] = c; sk[l] = a; }
                }
            }
            __syncthreads();
        }
    }
    if (tid == 0 && n < TOPK) {
        const float* cm = out + OFF_CMAP + ((size_t)b << 19);
        int ptr = 0;
        for (int s = n; s < TOPK; s++) {
            while (__ldcg(&cm[ptr]) != 0.0f) ptr++;
            sfill[s] = ptr++;
        }
    }
    __syncthreads();
    for (int s = tid; s < TOPK; s += 1024) {
        bool valid = (s < n);
        float v; int pix;
        if (valid) {
            ull key = sk[s];
            unsigned ob = ~(unsigned)(key >> 32);
            unsigned bo = (ob & 0x80000000u) ? (ob ^ 0x80000000u) : ~ob;
            v = __uint_as_float(bo);
            pix = (int)((unsigned)key & (HWSZ-1));
        } else {
            v = f_ninf();
            pix = sfill[s];
        }
        int y = pix >> 10, x = pix & (WW-1);
        g_cx[b][s] = valid ? (float)x : 1000000000.0f;
        g_cy[b][s] = valid ? (float)y : 1000000000.0f;
        out[OFF_TOPV + b*TOPK + s] = v;
        out[OFF_CENTERS + (b*TOPK + s)*2 + 0] = (float)y;
        out[OFF_CENTERS + (b*TOPK + s)*2 + 1] = (float)x;
    }
}

// ---------------- K4: streaming softmax/argmax, 4 px/thread ----------------
__global__ void k4_softmax(const float* __restrict__ logits, float* __restrict__ out) {
    const int qp = blockIdx.x * blockDim.x + threadIdx.x;
    const int b = blockIdx.y;
    const float4* base = (const float4*)(logits + (size_t)b * NCLS * HWSZ);
    float m[4] = {f_ninf(), f_ninf(), f_ninf(), f_ninf()};
    int   am[4] = {0, 0, 0, 0};
    float s[4] = {0.f, 0.f, 0.f, 0.f};
    float e[4][10];
    #pragma unroll
    for (int c = 0; c < NCLS; c++) {
        float4 l = __ldg(&base[(size_t)c * (HWSZ/4) + qp]);
        float lv[4] = {l.x, l.y, l.z, l.w};
        #pragma unroll
        for (int k = 0; k < 4; k++) {
            if (lv[k] > m[k]) { m[k] = lv[k]; am[k] = c; }
            float ex = __expf(lv[k]);
            s[k] += ex;
            if (c >= 24) e[k][c - 24] = ex;
        }
    }
    ((float4*)(out + OFF_SEG  + (b << 19)))[qp] =
        make_float4((float)am[0], (float)am[1], (float)am[2], (float)am[3]);
    ((float4*)(out + OFF_INST + (b << 19)))[qp] = make_float4(0.f, 0.f, 0.f, 0.f);
    const int lane = threadIdx.x & 31;
    const unsigned below = (1u << lane) - 1u;
    unsigned mb[4]; int cnt[4];
    #pragma unroll
    for (int k = 0; k < 4; k++) {
        mb[k] = __ballot_sync(0xFFFFFFFFu, am[k] >= 24);
        cnt[k] = __popc(mb[k]);
    }
    int tot = cnt[0] + cnt[1] + cnt[2] + cnt[3];
    int base_i = 0;
    if (lane == 0 && tot) base_i = atomicAdd(&g_tcnt, tot);
    base_i = __shfl_sync(0xFFFFFFFFu, base_i, 0);
    int run = 0;
    #pragma unroll
    for (int k = 0; k < 4; k++) {
        if (am[k] >= 24) {
            int idx = base_i + run + __popc(mb[k] & below);
            float inv = 1.0f / s[k];
            g_tpix[idx] = ((unsigned)b << 19) | (unsigned)(4*qp + k);
            g_tcls[idx] = (unsigned char)am[k];
            #pragma unroll
            for (int j = 0; j < 10; j++) g_tprob[j][idx] = e[k][j] * inv;
        }
        run += cnt[k];
    }
}

// ---------------- K5: argmin + class counts + 10-class prob sums (single pass) ----------------
__global__ void k5_argmin(const float* __restrict__ reg, float* __restrict__ out) {
    __shared__ ull sncx2[BATCH][TOPK/2];
    __shared__ ull sncy2[BATCH][TOPK/2];
    __shared__ unsigned int scount[BATCH*TOPK*10];
    __shared__ float sps[BATCH*TOPK*10];
    const int tid = threadIdx.x;
    for (int i = tid; i < BATCH*(TOPK/2); i += blockDim.x) {
        int b = i / (TOPK/2), k = i % (TOPK/2);
        sncx2[b][k] = pk2(-g_cx[b][2*k], -g_cx[b][2*k + 1]);
        sncy2[b][k] = pk2(-g_cy[b][2*k], -g_cy[b][2*k + 1]);
    }
    for (int i = tid; i < BATCH*TOPK*10; i += blockDim.x) { scount[i] = 0; sps[i] = 0.0f; }
    __syncthreads();
    const int n = g_tcnt;
    for (int e = blockIdx.x * blockDim.x + tid; e < n; e += gridDim.x * blockDim.x) {
        unsigned gpix = g_tpix[e];
        int b = gpix >> 19;
        int pix = gpix & (HWSZ-1);
        int y = pix >> 10, x = pix & (WW-1);
        float rx = __ldg(&reg[(size_t)b * 2 * HWSZ + pix]);
        float ry = __ldg(&reg[(size_t)(b * 2 + 1) * HWSZ + pix]);
        float px = __fadd_rn((float)(x + 1), -rx);
        float py = __fadd_rn((float)(y + 1), -ry);
        ull px2 = pk2(px, px), py2 = pk2(py, py);
        float best = f_inf(); int bi = 0;
        #pragma unroll 4
        for (int i = 0; i < TOPK/2; i++) {
            ull dx2 = addf2(px2, sncx2[b][i]);
            ull dy2 = addf2(py2, sncy2[b][i]);
            ull d2  = addf2(mulf2(dx2, dx2), mulf2(dy2, dy2));
            float lo, hi; upk2(d2, lo, hi);
            if (lo < best) { best = lo; bi = 2*i; }
            if (hi < best) { best = hi; bi = 2*i + 1; }
        }
        out[OFF_INST + gpix] = (float)(bi + 1);
        int bin10 = (b*TOPK + bi)*10;
        atomicAdd(&scount[bin10 + (g_tcls[e] - 24)], 1u);
        #pragma unroll
        for (int j = 0; j < 10; j++)
            atomicAdd(&sps[bin10 + j], g_tprob[j][e]);
    }
    __syncthreads();
    for (int i = tid; i < BATCH*TOPK*10; i += blockDim.x) {
        unsigned v = scount[i];
        if (v) atomicAdd(&g_counts[i], v);
        float f = sps[i];
        if (f != 0.0f) atomicAdd(&g_psum10[i], f);
    }
}

// ---------------- KFIN: per-instance class/size/prob ----------------
__global__ void kfin(float* __restrict__ out) {
    int t = blockIdx.x * blockDim.x + threadIdx.x;
    if (t >= BATCH*TOPK) return;
    unsigned size = 0, cm = 0;
    int ci = 0;
    #pragma unroll
    for (int c = 0; c < 10; c++) {
        unsigned v = g_counts[t*10 + c];
        size += v;
        if (v > cm) { cm = v; ci = c; }
    }
    int cls = (size == 0) ? 0 : (24 + ci);
    out[OFF_ICLS + t] = (float)cls;
    out[OFF_ISZ  + t] = (float)size;
    out[OFF_IPROB + t] = g_psum10[t*10 + ci] / fmaxf((float)size, 1.0f);
}

extern "C" void kernel_launch(void* const* d_in, const int* in_sizes, int n_in,
                              void* d_out, int out_size) {
    const float* logits = (const float*)d_in[0];
    const float* reg    = (const float*)d_in[2];
    float* out = (float*)d_out;

    static cudaStream_t s2 = nullptr;
    static cudaEvent_t ev0 = nullptr, ev2 = nullptr;
    if (s2 == nullptr) {
        cudaStreamCreateWithFlags(&s2, cudaStreamNonBlocking);
        cudaEventCreateWithFlags(&ev0, cudaEventDisableTiming);
        cudaEventCreateWithFlags(&ev2, cudaEventDisableTiming);
    }

    double s = 0.0;
    for (int dy = -5; dy <= 5; dy++)
        for (int dx = -5; dx <= 5; dx++)
            if (dx*dx + dy*dy <= 25) s += sqrt((double)(dx*dx + dy*dy));
    double thr = s / 81.0;
    float negthr = (float)(-thr - 1.0);

    k0_reset<<<1, 512>>>();
    cudaEventRecord(ev0, 0);
    cudaStreamWaitEvent(s2, ev0, 0);

    // branch B (softmax, DRAM-bound) on s2
    k4_softmax<<<dim3(HWSZ/1024, BATCH), 256, 0, s2>>>(logits, out);
    cudaEventRecord(ev2, s2);

    // branch A (vote pipeline, math-bound) on default stream
    k1_vote<<<dim3(WW/64, HH/8, BATCH), dim3(32, 8)>>>(reg);
    k2_nms<<<dim3(WW/32, HH/32, BATCH), dim3(32, 32)>>>(out, negthr);

    // join
    cudaStreamWaitEvent(0, ev2, 0);
    k5_argmin<<<296, 256>>>(reg, out);
    kfin<<<1, 512>>>(out);
}

// round 13
// speedup vs baseline: 1.3128x; 1.3128x over previous
#include <cuda_runtime.h>
#include <math.h>

#define BATCH 2
#define NCLS  34
#define HH    512
#define WW    1024
#define HWSZ  (HH*WW)          // 524288 = 2^19
#define TOPK  200
#define RAD   5

#define OFF_INST    0
#define OFF_SEG     (BATCH*HWSZ)
#define OFF_CENTERS (2*BATCH*HWSZ)
#define OFF_TOPV    (OFF_CENTERS + BATCH*TOPK*2)
#define OFF_ICLS    (OFF_TOPV + BATCH*TOPK)
#define OFF_IPROB   (OFF_ICLS + BATCH*TOPK)
#define OFF_ISZ     (OFF_IPROB + BATCH*TOPK)
#define OFF_CMAP    (OFF_ISZ + BATCH*TOPK)

__device__ float              g_vote[BATCH*HWSZ];
__device__ unsigned long long g_cand[BATCH][HWSZ];
__device__ int                g_cand_cnt[BATCH];
__device__ float              g_cx[BATCH][TOPK];
__device__ float              g_cy[BATCH][TOPK];
__device__ unsigned int       g_tpix[BATCH*HWSZ];
__device__ unsigned char      g_tcls[BATCH*HWSZ];
__device__ int                g_tinst[BATCH*HWSZ];
__device__ float              g_tprob[10][BATCH*HWSZ];
__device__ int                g_tcnt;
__device__ unsigned int       g_counts[BATCH*TOPK*10];
__device__ float              g_psum[BATCH*TOPK];
__device__ int                g_icls[BATCH*TOPK];

typedef unsigned long long ull;

__device__ __forceinline__ float f_inf()  { return __int_as_float(0x7f800000); }
__device__ __forceinline__ float f_ninf() { return __int_as_float(0xff800000); }

__device__ __forceinline__ ull pk2(float a, float b) {
    ull r; asm("mov.b64 %0, {%1,%2};" : "=l"(r) : "f"(a), "f"(b)); return r;
}
__device__ __forceinline__ void upk2(ull v, float& a, float& b) {
    asm("mov.b64 {%0,%1}, %2;" : "=f"(a), "=f"(b) : "l"(v));
}
__device__ __forceinline__ ull addf2(ull a, ull b) {
    ull r; asm("add.rn.f32x2 %0, %1, %2;" : "=l"(r) : "l"(a), "l"(b)); return r;
}
__device__ __forceinline__ ull mulf2(ull a, ull b) {
    ull r; asm("mul.rn.f32x2 %0, %1, %2;" : "=l"(r) : "l"(a), "l"(b)); return r;
}

// ---------------- K0: reset ----------------
__global__ void k0_reset() {
    int t = threadIdx.x;
    if (t < BATCH) g_cand_cnt[t] = 0;
    if (t == 0) g_tcnt = 0;
    for (int i = t; i < BATCH*TOPK*10; i += blockDim.x) g_counts[i] = 0;
    for (int i = t; i < BATCH*TOPK;    i += blockDim.x) g_psum[i] = 0.0f;
}

// ---------------- K1: vote map (bit-exact, f32x2, 2 px/thread) ----------------
__global__ void k1_vote(const float* __restrict__ reg) {
    __shared__ float snx[18][76];
    __shared__ float sny[18][76];
    const int b  = blockIdx.z;
    const int bx = blockIdx.x * 64, by = blockIdx.y * 8;
    const int tid = threadIdx.y * 32 + threadIdx.x;
    const float* rxp = reg + (size_t)b * 2 * HWSZ;
    const float* ryp = rxp + HWSZ;
    for (int i = tid; i < 18*74; i += 256) {
        int sy = i / 74, sx = i % 74;
        int gy = by + sy - RAD, gx = bx + sx - RAD;
        float vx = 0.f, vy = 0.f;
        if (gy >= 0 && gy < HH && gx >= 0 && gx < WW) {
            int p = gy * WW + gx;
            vx = rxp[p]; vy = ryp[p];
        }
        snx[sy][sx] = -vx;
        sny[sy][sx] = -vy;
    }
    __syncthreads();
    const int tx = threadIdx.x, ty = threadIdx.y;
    const int cb = 2 * tx;
    ull acc = pk2(0.0f, 0.0f);
    #pragma unroll
    for (int i = 0; i < 11; i++) {
        #pragma unroll
        for (int j = 0; j < 11; j++) {
            const int dy = i - 5, dx = j - 5;
            if (dx*dx + dy*dy <= 25) {
                float nx0 = snx[ty + i][cb + j];
                float nx1 = snx[ty + i][cb + j + 1];
                float ny0 = sny[ty + i][cb + j];
                float ny1 = sny[ty + i][cb + j + 1];
                ull ox2 = pk2((float)dx, (float)dx);
                ull oy2 = pk2((float)dy, (float)dy);
                ull ddx = addf2(ox2, pk2(nx0, nx1));
                ull ddy = addf2(oy2, pk2(ny0, ny1));
                ull d2  = addf2(mulf2(ddx, ddx), mulf2(ddy, ddy));
                float lo, hi; upk2(d2, lo, hi);
                float s0 = __fsqrt_rn(lo);
                float s1 = __fsqrt_rn(hi);
                acc = addf2(acc, pk2(s0, s1));
            }
        }
    }
    float a0, a1; upk2(acc, a0, a1);
    float q0 = __fdiv_rn(a0, 81.0f);
    float q1 = __fdiv_rn(a1, 81.0f);
    float v0 = __fadd_rn(-q0, -1.0f);
    float v1 = __fadd_rn(-q1, -1.0f);
    int idx = ((int)b << 19) + (by + ty) * WW + bx + cb;
    *reinterpret_cast<float2*>(&g_vote[idx]) = make_float2(v0, v1);
}

// ---------------- K2: fused 7x7 NMS + keep + candidate collect + center_map ----------------
__global__ void k2_nms(float* __restrict__ out, float negthr) {
    __shared__ float sv[14][40];
    __shared__ float rm[14][33];
    const int b  = blockIdx.z;
    const int bx = blockIdx.x * 32, by = blockIdx.y * 8;
    const int tid = threadIdx.y * 32 + threadIdx.x;
    for (int i = tid; i < 14*38; i += 256) {
        int sy = i / 38, sx = i % 38;
        int gy = by + sy - 3, gx = bx + sx - 3;
        float v = f_ninf();
        if (gy >= 0 && gy < HH && gx >= 0 && gx < WW)
            v = g_vote[((int)b << 19) + gy * WW + gx];
        sv[sy][sx] = v;
    }
    __syncthreads();
    for (int i = tid; i < 14*32; i += 256) {
        int sy = i / 32, sx = i % 32;
        float m = sv[sy][sx];
        #pragma unroll
        for (int d = 1; d < 7; d++) m = fmaxf(m, sv[sy][sx + d]);
        rm[sy][sx] = m;
    }
    __syncthreads();
    const int tx = threadIdx.x, ty = threadIdx.y;
    float v = sv[ty + 3][tx + 3];
    float p = rm[ty][tx];
    #pragma unroll
    for (int d = 1; d < 7; d++) p = fmaxf(p, rm[ty + d][tx]);
    bool keep = (p == v) && (v > negthr);
    int pix = (by + ty) * WW + (bx + tx);
    out[OFF_CMAP + ((int)b << 19) + pix] = keep ? v : 0.0f;
    if (keep) {
        unsigned bo = __float_as_uint(v);
        unsigned ob = ((int)bo < 0) ? ~bo : (bo ^ 0x80000000u);
        ull key = ((ull)(~ob) << 32) | (unsigned)pix;
        int pos = atomicAdd(&g_cand_cnt[b], 1);
        g_cand[b][pos] = key;
    }
}

// ---------------- K3: top-K per batch via radix select + rank-by-counting sort ----------------
__global__ void k3_topk(float* __restrict__ out) {
    const int b = blockIdx.x;
    const int n = g_cand_cnt[b];
    const int tid = threadIdx.x;
    __shared__ unsigned hist[256];
    __shared__ unsigned warpsum[8];
    __shared__ ull sk[512];
    __shared__ ull sorted[512];
    __shared__ int sfill[TOPK];
    __shared__ int scnt;
    __shared__ unsigned s_prefix;
    __shared__ int s_target;

    unsigned kth = 0xFFFFFFFFu;
    if (n > TOPK) {
        unsigned prefix = 0; int target = TOPK;
        #pragma unroll
        for (int shift = 24; shift >= 0; shift -= 8) {
            if (tid < 256) hist[tid] = 0;
            __syncthreads();
            unsigned pm = (shift == 24) ? 0u : (0xFFFFFFFFu << (shift + 8));
            for (int i = tid; i < n; i += 1024) {
                unsigned kv = (unsigned)(__ldg(&g_cand[b][i]) >> 32);
                if ((kv & pm) == prefix) atomicAdd(&hist[(kv >> shift) & 255u], 1u);
            }
            __syncthreads();
            unsigned h = 0, incl = 0;
            if (tid < 256) {
                h = hist[tid];
                incl = h;
                #pragma unroll
                for (int o = 1; o < 32; o <<= 1) {
                    unsigned t = __shfl_up_sync(0xFFFFFFFFu, incl, o);
                    if ((tid & 31) >= o) incl += t;
                }
                if ((tid & 31) == 31) warpsum[tid >> 5] = incl;
            }
            __syncthreads();
            if (tid < 8) {
                unsigned v = warpsum[tid];
                #pragma unroll
                for (int o = 1; o < 8; o <<= 1) {
                    unsigned t = __shfl_up_sync(0xFFu, v, o);
                    if (tid >= o) v += t;
                }
                warpsum[tid] = v;
            }
            __syncthreads();
            if (tid < 256) {
                unsigned tot = incl + ((tid >= 32) ? warpsum[(tid >> 5) - 1] : 0u);
                unsigned excl = tot - h;
                if ((int)excl < target && (int)tot >= target) {
                    s_prefix = prefix | ((unsigned)tid << shift);
                    s_target = target - (int)excl;
                }
            }
            __syncthreads();
            prefix = s_prefix; target = s_target;
            __syncthreads();
        }
        kth = prefix;
    }
    if (tid == 0) scnt = 0;
    __syncthreads();
    for (int i = tid; i < n; i += 1024) {
        ull key = __ldg(&g_cand[b][i]);
        if ((unsigned)(key >> 32) <= kth) {
            int pos = atomicAdd(&scnt, 1);
            if (pos < 512) sk[pos] = key;
        }
    }
    __syncthreads();
    int m = scnt; if (m > 512) m = 512;
    for (int i = tid; i < 512; i += 1024) if (i >= m) sk[i] = 0xFFFFFFFFFFFFFFFFull;
    __syncthreads();
    // rank-by-counting sort: real keys are unique (pixel id in low bits);
    // padding duplicates all land at rank >= m, which is never read (s < min(n,TOPK) <= m).
    if (tid < 512) {
        ull key = sk[tid];
        int rank = 0;
        #pragma unroll 8
        for (int j = 0; j < 512; j++) rank += (sk[j] < key) ? 1 : 0;
        sorted[rank] = key;
    }
    __syncthreads();
    if (tid == 0 && n < TOPK) {
        const float* cm = out + OFF_CMAP + ((size_t)b << 19);
        int ptr = 0;
        for (int s = n; s < TOPK; s++) {
            while (cm[ptr] != 0.0f) ptr++;
            sfill[s] = ptr++;
        }
    }
    __syncthreads();
    for (int s = tid; s < TOPK; s += 1024) {
        bool valid = (s < n);
        float v; int pix;
        if (valid) {
            ull key = sorted[s];
            unsigned ob = ~(unsigned)(key >> 32);
            unsigned bo = (ob & 0x80000000u) ? (ob ^ 0x80000000u) : ~ob;
            v = __uint_as_float(bo);
            pix = (int)((unsigned)key & (HWSZ-1));
        } else {
            v = f_ninf();
            pix = sfill[s];
        }
        int y = pix >> 10, x = pix & (WW-1);
        g_cx[b][s] = valid ? (float)x : 1000000000.0f;
        g_cy[b][s] = valid ? (float)y : 1000000000.0f;
        out[OFF_TOPV + b*TOPK + s] = v;
        out[OFF_CENTERS + (b*TOPK + s)*2 + 0] = (float)y;
        out[OFF_CENTERS + (b*TOPK + s)*2 + 1] = (float)x;
    }
}

// ---------------- K4: streaming softmax/argmax, 4 px/thread ----------------
__global__ void k4_softmax(const float* __restrict__ logits, float* __restrict__ out) {
    const int qp = blockIdx.x * blockDim.x + threadIdx.x;
    const int b = blockIdx.y;
    const float4* base = (const float4*)(logits + (size_t)b * NCLS * HWSZ);
    float m[4] = {f_ninf(), f_ninf(), f_ninf(), f_ninf()};
    int   am[4] = {0, 0, 0, 0};
    float s[4] = {0.f, 0.f, 0.f, 0.f};
    float e[4][10];
    #pragma unroll
    for (int c = 0; c < NCLS; c++) {
        float4 l = __ldg(&base[(size_t)c * (HWSZ/4) + qp]);
        float lv[4] = {l.x, l.y, l.z, l.w};
        #pragma unroll
        for (int k = 0; k < 4; k++) {
            if (lv[k] > m[k]) { m[k] = lv[k]; am[k] = c; }
            float ex = __expf(lv[k]);
            s[k] += ex;
            if (c >= 24) e[k][c - 24] = ex;
        }
    }
    ((float4*)(out + OFF_SEG  + (b << 19)))[qp] =
        make_float4((float)am[0], (float)am[1], (float)am[2], (float)am[3]);
    ((float4*)(out + OFF_INST + (b << 19)))[qp] = make_float4(0.f, 0.f, 0.f, 0.f);
    const int lane = threadIdx.x & 31;
    const unsigned below = (1u << lane) - 1u;
    unsigned mb[4]; int cnt[4];
    #pragma unroll
    for (int k = 0; k < 4; k++) {
        mb[k] = __ballot_sync(0xFFFFFFFFu, am[k] >= 24);
        cnt[k] = __popc(mb[k]);
    }
    int tot = cnt[0] + cnt[1] + cnt[2] + cnt[3];
    int base_i = 0;
    if (lane == 0 && tot) base_i = atomicAdd(&g_tcnt, tot);
    base_i = __shfl_sync(0xFFFFFFFFu, base_i, 0);
    int run = 0;
    #pragma unroll
    for (int k = 0; k < 4; k++) {
        if (am[k] >= 24) {
            int idx = base_i + run + __popc(mb[k] & below);
            float inv = 1.0f / s[k];
            g_tpix[idx] = ((unsigned)b << 19) | (unsigned)(4*qp + k);
            g_tcls[idx] = (unsigned char)am[k];
            #pragma unroll
            for (int j = 0; j < 10; j++) g_tprob[j][idx] = e[k][j] * inv;
        }
        run += cnt[k];
    }
}

// ---------------- K5: argmin over centers (f32x2, bit-exact) + counts ----------------
__global__ void k5_argmin(const float* __restrict__ reg, float* __restrict__ out) {
    __shared__ ull sncx2[BATCH][TOPK/2];
    __shared__ ull sncy2[BATCH][TOPK/2];
    __shared__ unsigned int scount[BATCH*TOPK*10];
    const int tid = threadIdx.x;
    for (int i = tid; i < BATCH*(TOPK/2); i += blockDim.x) {
        int b = i / (TOPK/2), k = i % (TOPK/2);
        sncx2[b][k] = pk2(-g_cx[b][2*k], -g_cx[b][2*k + 1]);
        sncy2[b][k] = pk2(-g_cy[b][2*k], -g_cy[b][2*k + 1]);
    }
    for (int i = tid; i < BATCH*TOPK*10; i += blockDim.x) scount[i] = 0;
    __syncthreads();
    const int n = g_tcnt;
    for (int e = blockIdx.x * blockDim.x + tid; e < n; e += gridDim.x * blockDim.x) {
        unsigned gpix = g_tpix[e];
        int b = gpix >> 19;
        int pix = gpix & (HWSZ-1);
        int y = pix >> 10, x = pix & (WW-1);
        float rx = __ldg(&reg[(size_t)b * 2 * HWSZ + pix]);
        float ry = __ldg(&reg[(size_t)(b * 2 + 1) * HWSZ + pix]);
        float px = __fadd_rn((float)(x + 1), -rx);
        float py = __fadd_rn((float)(y + 1), -ry);
        ull px2 = pk2(px, px), py2 = pk2(py, py);
        float best = f_inf(); int bi = 0;
        #pragma unroll 4
        for (int i = 0; i < TOPK/2; i++) {
            ull dx2 = addf2(px2, sncx2[b][i]);
            ull dy2 = addf2(py2, sncy2[b][i]);
            ull d2  = addf2(mulf2(dx2, dx2), mulf2(dy2, dy2));
            float lo, hi; upk2(d2, lo, hi);
            if (lo < best) { best = lo; bi = 2*i; }
            if (hi < best) { best = hi; bi = 2*i + 1; }
        }
        out[OFF_INST + gpix] = (float)(bi + 1);
        g_tinst[e] = bi + 1;
        int cls = g_tcls[e];
        atomicAdd(&scount[(b*TOPK + bi)*10 + (cls - 24)], 1u);
    }
    __syncthreads();
    for (int i = tid; i < BATCH*TOPK*10; i += blockDim.x) {
        unsigned v = scount[i];
        if (v) atomicAdd(&g_counts[i], v);
    }
}

// ---------------- K6: per-instance class/size ----------------
__global__ void k6_cls(float* __restrict__ out) {
    int t = blockIdx.x * blockDim.x + threadIdx.x;
    if (t >= BATCH*TOPK) return;
    unsigned size = 0, cm = 0;
    int ci = 0;
    #pragma unroll
    for (int c = 0; c < 10; c++) {
        unsigned v = g_counts[t*10 + c];
        size += v;
        if (v > cm) { cm = v; ci = c; }
    }
    int cls = (size == 0) ? 0 : (24 + ci);
    g_icls[t] = cls;
    out[OFF_ICLS + t] = (float)cls;
    out[OFF_ISZ  + t] = (float)size;
}

// ---------------- K7: prob sums for selected class ----------------
__global__ void k7_psum() {
    __shared__ int   sicls[BATCH*TOPK];
    __shared__ float sps[BATCH*TOPK];
    const int tid = threadIdx.x;
    for (int i = tid; i < BATCH*TOPK; i += blockDim.x) { sicls[i] = g_icls[i]; sps[i] = 0.0f; }
    __syncthreads();
    const int n = g_tcnt;
    for (int e = blockIdx.x * blockDim.x + tid; e < n; e += gridDim.x * blockDim.x) {
        unsigned gpix = g_tpix[e];
        int b = gpix >> 19;
        int inst = g_tinst[e];
        int bin = b*TOPK + inst - 1;
        int c = sicls[bin];
        float p = g_tprob[c - 24][e];
        atomicAdd(&sps[bin], p);
    }
    __syncthreads();
    for (int i = tid; i < BATCH*TOPK; i += blockDim.x)
        if (sps[i] != 0.0f) atomicAdd(&g_psum[i], sps[i]);
}

// ---------------- K8: inst_seg_prob ----------------
__global__ void k8_final(float* __restrict__ out) {
    int t = blockIdx.x * blockDim.x + threadIdx.x;
    if (t >= BATCH*TOPK) return;
    float size = out[OFF_ISZ + t];
    out[OFF_IPROB + t] = g_psum[t] / fmaxf(size, 1.0f);
}

extern "C" void kernel_launch(void* const* d_in, const int* in_sizes, int n_in,
                              void* d_out, int out_size) {
    const float* logits = (const float*)d_in[0];
    const float* reg    = (const float*)d_in[2];
    float* out = (float*)d_out;

    static cudaStream_t s2 = nullptr;
    static cudaEvent_t ev0 = nullptr, ev2 = nullptr;
    if (s2 == nullptr) {
        cudaStreamCreateWithFlags(&s2, cudaStreamNonBlocking);
        cudaEventCreateWithFlags(&ev0, cudaEventDisableTiming);
        cudaEventCreateWithFlags(&ev2, cudaEventDisableTiming);
    }

    double s = 0.0;
    for (int dy = -5; dy <= 5; dy++)
        for (int dx = -5; dx <= 5; dx++)
            if (dx*dx + dy*dy <= 25) s += sqrt((double)(dx*dx + dy*dy));
    double thr = s / 81.0;
    float negthr = (float)(-thr - 1.0);

    k0_reset<<<1, 512>>>();
    cudaEventRecord(ev0, 0);
    cudaStreamWaitEvent(s2, ev0, 0);

    // branch B (softmax, DRAM-bound) on s2
    k4_softmax<<<dim3(HWSZ/1024, BATCH), 256, 0, s2>>>(logits, out);
    cudaEventRecord(ev2, s2);

    // branch A (vote pipeline, math-bound) on default stream
    k1_vote<<<dim3(WW/64, HH/8, BATCH), dim3(32, 8)>>>(reg);
    k2_nms<<<dim3(WW/32, HH/8, BATCH), dim3(32, 8)>>>(out, negthr);
    k3_topk<<<BATCH, 1024>>>(out);

    // join
    cudaStreamWaitEvent(0, ev2, 0);
    k5_argmin<<<296, 256>>>(reg, out);
    k6_cls<<<1, 512>>>(out);
    k7_psum<<<296, 256>>>();
    k8_final<<<1, 512>>>(out);
}

// round 14
// speedup vs baseline: 1.3187x; 1.0044x over previous
#include <cuda_runtime.h>
#include <math.h>

#define BATCH 2
#define NCLS  34
#define HH    512
#define WW    1024
#define HWSZ  (HH*WW)          // 524288 = 2^19
#define TOPK  200
#define RAD   5

#define OFF_INST    0
#define OFF_SEG     (BATCH*HWSZ)
#define OFF_CENTERS (2*BATCH*HWSZ)
#define OFF_TOPV    (OFF_CENTERS + BATCH*TOPK*2)
#define OFF_ICLS    (OFF_TOPV + BATCH*TOPK)
#define OFF_IPROB   (OFF_ICLS + BATCH*TOPK)
#define OFF_ISZ     (OFF_IPROB + BATCH*TOPK)
#define OFF_CMAP    (OFF_ISZ + BATCH*TOPK)

__device__ float              g_vote[BATCH*HWSZ];
__device__ unsigned long long g_cand[BATCH][HWSZ];
__device__ int                g_cand_cnt[BATCH];
__device__ float              g_cx[BATCH][TOPK];
__device__ float              g_cy[BATCH][TOPK];
__device__ unsigned int       g_tpix[BATCH*HWSZ];
__device__ unsigned char      g_tcls[BATCH*HWSZ];
__device__ int                g_tinst[BATCH*HWSZ];
__device__ float              g_tprob[10][BATCH*HWSZ];
__device__ int                g_tcnt;
__device__ unsigned int       g_counts[BATCH*TOPK*10];
__device__ float              g_psum[BATCH*TOPK];
__device__ int                g_icls[BATCH*TOPK];

typedef unsigned long long ull;

__device__ __forceinline__ float f_inf()  { return __int_as_float(0x7f800000); }
__device__ __forceinline__ float f_ninf() { return __int_as_float(0xff800000); }

__device__ __forceinline__ ull pk2(float a, float b) {
    ull r; asm("mov.b64 %0, {%1,%2};" : "=l"(r) : "f"(a), "f"(b)); return r;
}
__device__ __forceinline__ void upk2(ull v, float& a, float& b) {
    asm("mov.b64 {%0,%1}, %2;" : "=f"(a), "=f"(b) : "l"(v));
}
__device__ __forceinline__ ull addf2(ull a, ull b) {
    ull r; asm("add.rn.f32x2 %0, %1, %2;" : "=l"(r) : "l"(a), "l"(b)); return r;
}
__device__ __forceinline__ ull mulf2(ull a, ull b) {
    ull r; asm("mul.rn.f32x2 %0, %1, %2;" : "=l"(r) : "l"(a), "l"(b)); return r;
}

// ---------------- K0: reset ----------------
__global__ void k0_reset() {
    int t = threadIdx.x;
    if (t < BATCH) g_cand_cnt[t] = 0;
    if (t == 0) g_tcnt = 0;
    for (int i = t; i < BATCH*TOPK*10; i += blockDim.x) g_counts[i] = 0;
    for (int i = t; i < BATCH*TOPK;    i += blockDim.x) g_psum[i] = 0.0f;
}

// ---------------- K1: vote map (bit-exact, f32x2, 2 px/thread, div-free halo) ----------------
__global__ void k1_vote(const float* __restrict__ reg) {
    __shared__ float snx[18][76];
    __shared__ float sny[18][76];
    const int b  = blockIdx.z;
    const int bx = blockIdx.x * 64, by = blockIdx.y * 8;
    const int tx = threadIdx.x, ty = threadIdx.y;
    const float* rxp = reg + (size_t)b * 2 * HWSZ;
    const float* ryp = rxp + HWSZ;
    #pragma unroll
    for (int sy = ty; sy < 18; sy += 8) {
        int gy = by + sy - RAD;
        bool yok = (unsigned)gy < (unsigned)HH;
        int rowbase = gy * WW;
        #pragma unroll
        for (int sx = tx; sx < 74; sx += 32) {
            int gx = bx + sx - RAD;
            float vx = 0.f, vy = 0.f;
            if (yok && (unsigned)gx < (unsigned)WW) {
                int p = rowbase + gx;
                vx = rxp[p]; vy = ryp[p];
            }
            snx[sy][sx] = -vx;
            sny[sy][sx] = -vy;
        }
    }
    __syncthreads();
    const int cb = 2 * tx;
    ull acc = pk2(0.0f, 0.0f);
    #pragma unroll
    for (int i = 0; i < 11; i++) {
        #pragma unroll
        for (int j = 0; j < 11; j++) {
            const int dy = i - 5, dx = j - 5;
            if (dx*dx + dy*dy <= 25) {
                float nx0 = snx[ty + i][cb + j];
                float nx1 = snx[ty + i][cb + j + 1];
                float ny0 = sny[ty + i][cb + j];
                float ny1 = sny[ty + i][cb + j + 1];
                ull ox2 = pk2((float)dx, (float)dx);
                ull oy2 = pk2((float)dy, (float)dy);
                ull ddx = addf2(ox2, pk2(nx0, nx1));
                ull ddy = addf2(oy2, pk2(ny0, ny1));
                ull d2  = addf2(mulf2(ddx, ddx), mulf2(ddy, ddy));
                float lo, hi; upk2(d2, lo, hi);
                float s0 = __fsqrt_rn(lo);
                float s1 = __fsqrt_rn(hi);
                acc = addf2(acc, pk2(s0, s1));
            }
        }
    }
    float a0, a1; upk2(acc, a0, a1);
    float q0 = __fdiv_rn(a0, 81.0f);
    float q1 = __fdiv_rn(a1, 81.0f);
    float v0 = __fadd_rn(-q0, -1.0f);
    float v1 = __fadd_rn(-q1, -1.0f);
    int idx = ((int)b << 19) + (by + ty) * WW + bx + cb;
    *reinterpret_cast<float2*>(&g_vote[idx]) = make_float2(v0, v1);
}

// ---------------- K2: fused 7x7 NMS (div-free halo) ----------------
__global__ void k2_nms(float* __restrict__ out, float negthr) {
    __shared__ float sv[14][40];
    __shared__ float rm[14][33];
    const int b  = blockIdx.z;
    const int bx = blockIdx.x * 32, by = blockIdx.y * 8;
    const int tx = threadIdx.x, ty = threadIdx.y;
    #pragma unroll
    for (int sy = ty; sy < 14; sy += 8) {
        int gy = by + sy - 3;
        bool yok = (unsigned)gy < (unsigned)HH;
        int rowbase = ((int)b << 19) + gy * WW;
        #pragma unroll
        for (int sx = tx; sx < 38; sx += 32) {
            int gx = bx + sx - 3;
            float v = f_ninf();
            if (yok && (unsigned)gx < (unsigned)WW)
                v = g_vote[rowbase + gx];
            sv[sy][sx] = v;
        }
    }
    __syncthreads();
    #pragma unroll
    for (int sy = ty; sy < 14; sy += 8) {
        float m = sv[sy][tx];
        #pragma unroll
        for (int d = 1; d < 7; d++) m = fmaxf(m, sv[sy][tx + d]);
        rm[sy][tx] = m;
    }
    __syncthreads();
    float v = sv[ty + 3][tx + 3];
    float p = rm[ty][tx];
    #pragma unroll
    for (int d = 1; d < 7; d++) p = fmaxf(p, rm[ty + d][tx]);
    bool keep = (p == v) && (v > negthr);
    int pix = (by + ty) * WW + (bx + tx);
    out[OFF_CMAP + ((int)b << 19) + pix] = keep ? v : 0.0f;
    if (keep) {
        unsigned bo = __float_as_uint(v);
        unsigned ob = ((int)bo < 0) ? ~bo : (bo ^ 0x80000000u);
        ull key = ((ull)(~ob) << 32) | (unsigned)pix;
        int pos = atomicAdd(&g_cand_cnt[b], 1);
        g_cand[b][pos] = key;
    }
}

// ---------------- K3: top-K per batch via radix select + rank-by-counting sort ----------------
__global__ void k3_topk(float* __restrict__ out) {
    const int b = blockIdx.x;
    const int n = g_cand_cnt[b];
    const int tid = threadIdx.x;
    __shared__ unsigned hist[256];
    __shared__ unsigned warpsum[8];
    __shared__ ull sk[512];
    __shared__ ull sorted[512];
    __shared__ int sfill[TOPK];
    __shared__ int scnt;
    __shared__ unsigned s_prefix;
    __shared__ int s_target;

    unsigned kth = 0xFFFFFFFFu;
    if (n > TOPK) {
        unsigned prefix = 0; int target = TOPK;
        #pragma unroll
        for (int shift = 24; shift >= 0; shift -= 8) {
            if (tid < 256) hist[tid] = 0;
            __syncthreads();
            unsigned pm = (shift == 24) ? 0u : (0xFFFFFFFFu << (shift + 8));
            for (int i = tid; i < n; i += 1024) {
                unsigned kv = (unsigned)(__ldg(&g_cand[b][i]) >> 32);
                if ((kv & pm) == prefix) atomicAdd(&hist[(kv >> shift) & 255u], 1u);
            }
            __syncthreads();
            unsigned h = 0, incl = 0;
            if (tid < 256) {
                h = hist[tid];
                incl = h;
                #pragma unroll
                for (int o = 1; o < 32; o <<= 1) {
                    unsigned t = __shfl_up_sync(0xFFFFFFFFu, incl, o);
                    if ((tid & 31) >= o) incl += t;
                }
                if ((tid & 31) == 31) warpsum[tid >> 5] = incl;
            }
            __syncthreads();
            if (tid < 8) {
                unsigned v = warpsum[tid];
                #pragma unroll
                for (int o = 1; o < 8; o <<= 1) {
                    unsigned t = __shfl_up_sync(0xFFu, v, o);
                    if (tid >= o) v += t;
                }
                warpsum[tid] = v;
            }
            __syncthreads();
            if (tid < 256) {
                unsigned tot = incl + ((tid >= 32) ? warpsum[(tid >> 5) - 1] : 0u);
                unsigned excl = tot - h;
                if ((int)excl < target && (int)tot >= target) {
                    s_prefix = prefix | ((unsigned)tid << shift);
                    s_target = target - (int)excl;
                }
            }
            __syncthreads();
            prefix = s_prefix; target = s_target;
            __syncthreads();
        }
        kth = prefix;
    }
    if (tid == 0) scnt = 0;
    __syncthreads();
    for (int i = tid; i < n; i += 1024) {
        ull key = __ldg(&g_cand[b][i]);
        if ((unsigned)(key >> 32) <= kth) {
            int pos = atomicAdd(&scnt, 1);
            if (pos < 512) sk[pos] = key;
        }
    }
    __syncthreads();
    int m = scnt; if (m > 512) m = 512;
    for (int i = tid; i < 512; i += 1024) if (i >= m) sk[i] = 0xFFFFFFFFFFFFFFFFull;
    __syncthreads();
    if (tid < 512) {
        ull key = sk[tid];
        int rank = 0;
        #pragma unroll 8
        for (int j = 0; j < 512; j++) rank += (sk[j] < key) ? 1 : 0;
        sorted[rank] = key;
    }
    __syncthreads();
    if (tid == 0 && n < TOPK) {
        const float* cm = out + OFF_CMAP + ((size_t)b << 19);
        int ptr = 0;
        for (int s = n; s < TOPK; s++) {
            while (cm[ptr] != 0.0f) ptr++;
            sfill[s] = ptr++;
        }
    }
    __syncthreads();
    for (int s = tid; s < TOPK; s += 1024) {
        bool valid = (s < n);
        float v; int pix;
        if (valid) {
            ull key = sorted[s];
            unsigned ob = ~(unsigned)(key >> 32);
            unsigned bo = (ob & 0x80000000u) ? (ob ^ 0x80000000u) : ~ob;
            v = __uint_as_float(bo);
            pix = (int)((unsigned)key & (HWSZ-1));
        } else {
            v = f_ninf();
            pix = sfill[s];
        }
        int y = pix >> 10, x = pix & (WW-1);
        g_cx[b][s] = valid ? (float)x : 1000000000.0f;
        g_cy[b][s] = valid ? (float)y : 1000000000.0f;
        out[OFF_TOPV + b*TOPK + s] = v;
        out[OFF_CENTERS + (b*TOPK + s)*2 + 0] = (float)y;
        out[OFF_CENTERS + (b*TOPK + s)*2 + 1] = (float)x;
    }
}

// ---------------- K4: streaming softmax/argmax, 4 px/thread ----------------
__global__ void k4_softmax(const float* __restrict__ logits, float* __restrict__ out) {
    const int qp = blockIdx.x * blockDim.x + threadIdx.x;
    const int b = blockIdx.y;
    const float4* base = (const float4*)(logits + (size_t)b * NCLS * HWSZ);
    float m[4] = {f_ninf(), f_ninf(), f_ninf(), f_ninf()};
    int   am[4] = {0, 0, 0, 0};
    float s[4] = {0.f, 0.f, 0.f, 0.f};
    float e[4][10];
    #pragma unroll
    for (int c = 0; c < NCLS; c++) {
        float4 l = __ldg(&base[(size_t)c * (HWSZ/4) + qp]);
        float lv[4] = {l.x, l.y, l.z, l.w};
        #pragma unroll
        for (int k = 0; k < 4; k++) {
            if (lv[k] > m[k]) { m[k] = lv[k]; am[k] = c; }
            float ex = __expf(lv[k]);
            s[k] += ex;
            if (c >= 24) e[k][c - 24] = ex;
        }
    }
    ((float4*)(out + OFF_SEG  + (b << 19)))[qp] =
        make_float4((float)am[0], (float)am[1], (float)am[2], (float)am[3]);
    ((float4*)(out + OFF_INST + (b << 19)))[qp] = make_float4(0.f, 0.f, 0.f, 0.f);
    const int lane = threadIdx.x & 31;
    const unsigned below = (1u << lane) - 1u;
    unsigned mb[4]; int cnt[4];
    #pragma unroll
    for (int k = 0; k < 4; k++) {
        mb[k] = __ballot_sync(0xFFFFFFFFu, am[k] >= 24);
        cnt[k] = __popc(mb[k]);
    }
    int tot = cnt[0] + cnt[1] + cnt[2] + cnt[3];
    int base_i = 0;
    if (lane == 0 && tot) base_i = atomicAdd(&g_tcnt, tot);
    base_i = __shfl_sync(0xFFFFFFFFu, base_i, 0);
    int run = 0;
    #pragma unroll
    for (int k = 0; k < 4; k++) {
        if (am[k] >= 24) {
            int idx = base_i + run + __popc(mb[k] & below);
            float inv = 1.0f / s[k];
            g_tpix[idx] = ((unsigned)b << 19) | (unsigned)(4*qp + k);
            g_tcls[idx] = (unsigned char)am[k];
            #pragma unroll
            for (int j = 0; j < 10; j++) g_tprob[j][idx] = e[k][j] * inv;
        }
        run += cnt[k];
    }
}

// ---------------- K5: argmin over centers (f32x2, bit-exact) + counts ----------------
__global__ void k5_argmin(const float* __restrict__ reg, float* __restrict__ out) {
    __shared__ ull sncx2[BATCH][TOPK/2];
    __shared__ ull sncy2[BATCH][TOPK/2];
    __shared__ unsigned int scount[BATCH*TOPK*10];
    const int tid = threadIdx.x;
    for (int i = tid; i < BATCH*(TOPK/2); i += blockDim.x) {
        int b = i / (TOPK/2), k = i % (TOPK/2);
        sncx2[b][k] = pk2(-g_cx[b][2*k], -g_cx[b][2*k + 1]);
        sncy2[b][k] = pk2(-g_cy[b][2*k], -g_cy[b][2*k + 1]);
    }
    for (int i = tid; i < BATCH*TOPK*10; i += blockDim.x) scount[i] = 0;
    __syncthreads();
    const int n = g_tcnt;
    for (int e = blockIdx.x * blockDim.x + tid; e < n; e += gridDim.x * blockDim.x) {
        unsigned gpix = g_tpix[e];
        int b = gpix >> 19;
        int pix = gpix & (HWSZ-1);
        int y = pix >> 10, x = pix & (WW-1);
        float rx = __ldg(&reg[(size_t)b * 2 * HWSZ + pix]);
        float ry = __ldg(&reg[(size_t)(b * 2 + 1) * HWSZ + pix]);
        float px = __fadd_rn((float)(x + 1), -rx);
        float py = __fadd_rn((float)(y + 1), -ry);
        ull px2 = pk2(px, px), py2 = pk2(py, py);
        float best = f_inf(); int bi = 0;
        #pragma unroll 4
        for (int i = 0; i < TOPK/2; i++) {
            ull dx2 = addf2(px2, sncx2[b][i]);
            ull dy2 = addf2(py2, sncy2[b][i]);
            ull d2  = addf2(mulf2(dx2, dx2), mulf2(dy2, dy2));
            float lo, hi; upk2(d2, lo, hi);
            if (lo < best) { best = lo; bi = 2*i; }
            if (hi < best) { best = hi; bi = 2*i + 1; }
        }
        out[OFF_INST + gpix] = (float)(bi + 1);
        g_tinst[e] = bi + 1;
        int cls = g_tcls[e];
        atomicAdd(&scount[(b*TOPK + bi)*10 + (cls - 24)], 1u);
    }
    __syncthreads();
    for (int i = tid; i < BATCH*TOPK*10; i += blockDim.x) {
        unsigned v = scount[i];
        if (v) atomicAdd(&g_counts[i], v);
    }
}

// ---------------- K6: per-instance class/size ----------------
__global__ void k6_cls(float* __restrict__ out) {
    int t = blockIdx.x * blockDim.x + threadIdx.x;
    if (t >= BATCH*TOPK) return;
    unsigned size = 0, cm = 0;
    int ci = 0;
    #pragma unroll
    for (int c = 0; c < 10; c++) {
        unsigned v = g_counts[t*10 + c];
        size += v;
        if (v > cm) { cm = v; ci = c; }
    }
    int cls = (size == 0) ? 0 : (24 + ci);
    g_icls[t] = cls;
    out[OFF_ICLS + t] = (float)cls;
    out[OFF_ISZ  + t] = (float)size;
}

// ---------------- K7: prob sums for selected class ----------------
__global__ void k7_psum() {
    __shared__ int   sicls[BATCH*TOPK];
    __shared__ float sps[BATCH*TOPK];
    const int tid = threadIdx.x;
    for (int i = tid; i < BATCH*TOPK; i += blockDim.x) { sicls[i] = g_icls[i]; sps[i] = 0.0f; }
    __syncthreads();
    const int n = g_tcnt;
    for (int e = blockIdx.x * blockDim.x + tid; e < n; e += gridDim.x * blockDim.x) {
        unsigned gpix = g_tpix[e];
        int b = gpix >> 19;
        int inst = g_tinst[e];
        int bin = b*TOPK + inst - 1;
        int c = sicls[bin];
        float p = g_tprob[c - 24][e];
        atomicAdd(&sps[bin], p);
    }
    __syncthreads();
    for (int i = tid; i < BATCH*TOPK; i += blockDim.x)
        if (sps[i] != 0.0f) atomicAdd(&g_psum[i], sps[i]);
}

// ---------------- K8: inst_seg_prob ----------------
__global__ void k8_final(float* __restrict__ out) {
    int t = blockIdx.x * blockDim.x + threadIdx.x;
    if (t >= BATCH*TOPK) return;
    float size = out[OFF_ISZ + t];
    out[OFF_IPROB + t] = g_psum[t] / fmaxf(size, 1.0f);
}

extern "C" void kernel_launch(void* const* d_in, const int* in_sizes, int n_in,
                              void* d_out, int out_size) {
    const float* logits = (const float*)d_in[0];
    const float* reg    = (const float*)d_in[2];
    float* out = (float*)d_out;

    static cudaStream_t s2 = nullptr;
    static cudaEvent_t ev0 = nullptr, ev2 = nullptr;
    if (s2 == nullptr) {
        cudaStreamCreateWithFlags(&s2, cudaStreamNonBlocking);
        cudaEventCreateWithFlags(&ev0, cudaEventDisableTiming);
        cudaEventCreateWithFlags(&ev2, cudaEventDisableTiming);
    }

    double s = 0.0;
    for (int dy = -5; dy <= 5; dy++)
        for (int dx = -5; dx <= 5; dx++)
            if (dx*dx + dy*dy <= 25) s += sqrt((double)(dx*dx + dy*dy));
    double thr = s / 81.0;
    float negthr = (float)(-thr - 1.0);

    k0_reset<<<1, 512>>>();
    cudaEventRecord(ev0, 0);
    cudaStreamWaitEvent(s2, ev0, 0);

    // branch B (softmax, DRAM-bound) on s2
    k4_softmax<<<dim3(HWSZ/1024, BATCH), 256, 0, s2>>>(logits, out);
    cudaEventRecord(ev2, s2);

    // branch A (vote pipeline, math-bound) on default stream
    k1_vote<<<dim3(WW/64, HH/8, BATCH), dim3(32, 8)>>>(reg);
    k2_nms<<<dim3(WW/32, HH/8, BATCH), dim3(32, 8)>>>(out, negthr);
    k3_topk<<<BATCH, 1024>>>(out);

    // join
    cudaStreamWaitEvent(0, ev2, 0);
    k5_argmin<<<296, 256>>>(reg, out);
    k6_cls<<<1, 512>>>(out);
    k7_psum<<<296, 256>>>();
    k8_final<<<1, 512>>>(out);
}

// round 15
// speedup vs baseline: 1.3261x; 1.0057x over previous
#include <cuda_runtime.h>
#include <cuda_fp16.h>
#include <math.h>

#define BATCH 2
#define NCLS  34
#define HH    512
#define WW    1024
#define HWSZ  (HH*WW)          // 524288 = 2^19
#define TOPK  200
#define RAD   5

#define OFF_INST    0
#define OFF_SEG     (BATCH*HWSZ)
#define OFF_CENTERS (2*BATCH*HWSZ)
#define OFF_TOPV    (OFF_CENTERS + BATCH*TOPK*2)
#define OFF_ICLS    (OFF_TOPV + BATCH*TOPK)
#define OFF_IPROB   (OFF_ICLS + BATCH*TOPK)
#define OFF_ISZ     (OFF_IPROB + BATCH*TOPK)
#define OFF_CMAP    (OFF_ISZ + BATCH*TOPK)

__device__ float              g_vote[BATCH*HWSZ];
__device__ unsigned long long g_cand[BATCH][HWSZ];
__device__ int                g_cand_cnt[BATCH];
__device__ float              g_cx[BATCH][TOPK];
__device__ float              g_cy[BATCH][TOPK];
__device__ unsigned int       g_tpix[BATCH*HWSZ];
__device__ unsigned char      g_tcls[BATCH*HWSZ];
__device__ int                g_tinst[BATCH*HWSZ];
__device__ __half             g_tprob[10][BATCH*HWSZ];
__device__ int                g_tcnt;
__device__ unsigned int       g_counts[BATCH*TOPK*10];
__device__ float              g_psum[BATCH*TOPK];
__device__ int                g_icls[BATCH*TOPK];

typedef unsigned long long ull;

__device__ __forceinline__ float f_inf()  { return __int_as_float(0x7f800000); }
__device__ __forceinline__ float f_ninf() { return __int_as_float(0xff800000); }

__device__ __forceinline__ ull pk2(float a, float b) {
    ull r; asm("mov.b64 %0, {%1,%2};" : "=l"(r) : "f"(a), "f"(b)); return r;
}
__device__ __forceinline__ void upk2(ull v, float& a, float& b) {
    asm("mov.b64 {%0,%1}, %2;" : "=f"(a), "=f"(b) : "l"(v));
}
__device__ __forceinline__ ull addf2(ull a, ull b) {
    ull r; asm("add.rn.f32x2 %0, %1, %2;" : "=l"(r) : "l"(a), "l"(b)); return r;
}
__device__ __forceinline__ ull mulf2(ull a, ull b) {
    ull r; asm("mul.rn.f32x2 %0, %1, %2;" : "=l"(r) : "l"(a), "l"(b)); return r;
}

// ---------------- K0: reset ----------------
__global__ void k0_reset() {
    int t = threadIdx.x;
    if (t < BATCH) g_cand_cnt[t] = 0;
    if (t == 0) g_tcnt = 0;
    for (int i = t; i < BATCH*TOPK*10; i += blockDim.x) g_counts[i] = 0;
    for (int i = t; i < BATCH*TOPK;    i += blockDim.x) g_psum[i] = 0.0f;
}

// ---------------- K1: vote map (bit-exact, f32x2, 2 px/thread, div-free halo) ----------------
__global__ void __launch_bounds__(256, 6) k1_vote(const float* __restrict__ reg) {
    __shared__ float snx[18][76];
    __shared__ float sny[18][76];
    const int b  = blockIdx.z;
    const int bx = blockIdx.x * 64, by = blockIdx.y * 8;
    const int tx = threadIdx.x, ty = threadIdx.y;
    const float* rxp = reg + (size_t)b * 2 * HWSZ;
    const float* ryp = rxp + HWSZ;
    #pragma unroll
    for (int sy = ty; sy < 18; sy += 8) {
        int gy = by + sy - RAD;
        bool yok = (unsigned)gy < (unsigned)HH;
        int rowbase = gy * WW;
        #pragma unroll
        for (int sx = tx; sx < 74; sx += 32) {
            int gx = bx + sx - RAD;
            float vx = 0.f, vy = 0.f;
            if (yok && (unsigned)gx < (unsigned)WW) {
                int p = rowbase + gx;
                vx = rxp[p]; vy = ryp[p];
            }
            snx[sy][sx] = -vx;
            sny[sy][sx] = -vy;
        }
    }
    __syncthreads();
    const int cb = 2 * tx;
    ull acc = pk2(0.0f, 0.0f);
    #pragma unroll
    for (int i = 0; i < 11; i++) {
        #pragma unroll
        for (int j = 0; j < 11; j++) {
            const int dy = i - 5, dx = j - 5;
            if (dx*dx + dy*dy <= 25) {
                float nx0 = snx[ty + i][cb + j];
                float nx1 = snx[ty + i][cb + j + 1];
                float ny0 = sny[ty + i][cb + j];
                float ny1 = sny[ty + i][cb + j + 1];
                ull ox2 = pk2((float)dx, (float)dx);
                ull oy2 = pk2((float)dy, (float)dy);
                ull ddx = addf2(ox2, pk2(nx0, nx1));
                ull ddy = addf2(oy2, pk2(ny0, ny1));
                ull d2  = addf2(mulf2(ddx, ddx), mulf2(ddy, ddy));
                float lo, hi; upk2(d2, lo, hi);
                float s0 = __fsqrt_rn(lo);
                float s1 = __fsqrt_rn(hi);
                acc = addf2(acc, pk2(s0, s1));
            }
        }
    }
    float a0, a1; upk2(acc, a0, a1);
    float q0 = __fdiv_rn(a0, 81.0f);
    float q1 = __fdiv_rn(a1, 81.0f);
    float v0 = __fadd_rn(-q0, -1.0f);
    float v1 = __fadd_rn(-q1, -1.0f);
    int idx = ((int)b << 19) + (by + ty) * WW + bx + cb;
    *reinterpret_cast<float2*>(&g_vote[idx]) = make_float2(v0, v1);
}

// ---------------- K2: fused 7x7 NMS, 2 px/thread (64x8 tile, div-free halo) ----------------
__global__ void k2_nms(float* __restrict__ out, float negthr) {
    __shared__ float sv[14][72];   // 70 used
    __shared__ float rm[14][64];
    const int b  = blockIdx.z;
    const int bx = blockIdx.x * 64, by = blockIdx.y * 8;
    const int tx = threadIdx.x, ty = threadIdx.y;
    #pragma unroll
    for (int sy = ty; sy < 14; sy += 8) {
        int gy = by + sy - 3;
        bool yok = (unsigned)gy < (unsigned)HH;
        int rowbase = ((int)b << 19) + gy * WW;
        #pragma unroll
        for (int sx = tx; sx < 70; sx += 32) {
            int gx = bx + sx - 3;
            float v = f_ninf();
            if (yok && (unsigned)gx < (unsigned)WW)
                v = g_vote[rowbase + gx];
            sv[sy][sx] = v;
        }
    }
    __syncthreads();
    #pragma unroll
    for (int sy = ty; sy < 14; sy += 8) {
        #pragma unroll
        for (int sx = tx; sx < 64; sx += 32) {
            float m = sv[sy][sx];
            #pragma unroll
            for (int d = 1; d < 7; d++) m = fmaxf(m, sv[sy][sx + d]);
            rm[sy][sx] = m;
        }
    }
    __syncthreads();
    const int cb = 2 * tx;
    float vv[2];
    #pragma unroll
    for (int k = 0; k < 2; k++) {
        int px = cb + k;
        float v = sv[ty + 3][px + 3];
        float p = rm[ty][px];
        #pragma unroll
        for (int d = 1; d < 7; d++) p = fmaxf(p, rm[ty + d][px]);
        bool keep = (p == v) && (v > negthr);
        vv[k] = keep ? v : 0.0f;
    }
    int pix0 = (by + ty) * WW + bx + cb;
    *reinterpret_cast<float2*>(&out[OFF_CMAP + ((int)b << 19) + pix0]) = make_float2(vv[0], vv[1]);
    #pragma unroll
    for (int k = 0; k < 2; k++) {
        if (vv[k] != 0.0f) {
            unsigned bo = __float_as_uint(vv[k]);
            unsigned ob = ((int)bo < 0) ? ~bo : (bo ^ 0x80000000u);
            ull key = ((ull)(~ob) << 32) | (unsigned)(pix0 + k);
            int pos = atomicAdd(&g_cand_cnt[b], 1);
            g_cand[b][pos] = key;
        }
    }
}

// ---------------- K3: top-K per batch via radix select + rank-by-counting sort ----------------
__global__ void k3_topk(float* __restrict__ out) {
    const int b = blockIdx.x;
    const int n = g_cand_cnt[b];
    const int tid = threadIdx.x;
    __shared__ unsigned hist[256];
    __shared__ unsigned warpsum[8];
    __shared__ ull sk[512];
    __shared__ ull sorted[512];
    __shared__ int sfill[TOPK];
    __shared__ int scnt;
    __shared__ unsigned s_prefix;
    __shared__ int s_target;

    unsigned kth = 0xFFFFFFFFu;
    if (n > TOPK) {
        unsigned prefix = 0; int target = TOPK;
        #pragma unroll
        for (int shift = 24; shift >= 0; shift -= 8) {
            if (tid < 256) hist[tid] = 0;
            __syncthreads();
            unsigned pm = (shift == 24) ? 0u : (0xFFFFFFFFu << (shift + 8));
            for (int i = tid; i < n; i += 1024) {
                unsigned kv = (unsigned)(__ldg(&g_cand[b][i]) >> 32);
                if ((kv & pm) == prefix) atomicAdd(&hist[(kv >> shift) & 255u], 1u);
            }
            __syncthreads();
            unsigned h = 0, incl = 0;
            if (tid < 256) {
                h = hist[tid];
                incl = h;
                #pragma unroll
                for (int o = 1; o < 32; o <<= 1) {
                    unsigned t = __shfl_up_sync(0xFFFFFFFFu, incl, o);
                    if ((tid & 31) >= o) incl += t;
                }
                if ((tid & 31) == 31) warpsum[tid >> 5] = incl;
            }
            __syncthreads();
            if (tid < 8) {
                unsigned v = warpsum[tid];
                #pragma unroll
                for (int o = 1; o < 8; o <<= 1) {
                    unsigned t = __shfl_up_sync(0xFFu, v, o);
                    if (tid >= o) v += t;
                }
                warpsum[tid] = v;
            }
            __syncthreads();
            if (tid < 256) {
                unsigned tot = incl + ((tid >= 32) ? warpsum[(tid >> 5) - 1] : 0u);
                unsigned excl = tot - h;
                if ((int)excl < target && (int)tot >= target) {
                    s_prefix = prefix | ((unsigned)tid << shift);
                    s_target = target - (int)excl;
                }
            }
            __syncthreads();
            prefix = s_prefix; target = s_target;
            __syncthreads();
        }
        kth = prefix;
    }
    if (tid == 0) scnt = 0;
    __syncthreads();
    for (int i = tid; i < n; i += 1024) {
        ull key = __ldg(&g_cand[b][i]);
        if ((unsigned)(key >> 32) <= kth) {
            int pos = atomicAdd(&scnt, 1);
            if (pos < 512) sk[pos] = key;
        }
    }
    __syncthreads();
    int m = scnt; if (m > 512) m = 512;
    for (int i = tid; i < 512; i += 1024) if (i >= m) sk[i] = 0xFFFFFFFFFFFFFFFFull;
    __syncthreads();
    if (tid < 512) {
        ull key = sk[tid];
        int rank = 0;
        #pragma unroll 8
        for (int j = 0; j < 512; j++) rank += (sk[j] < key) ? 1 : 0;
        sorted[rank] = key;
    }
    __syncthreads();
    if (tid == 0 && n < TOPK) {
        const float* cm = out + OFF_CMAP + ((size_t)b << 19);
        int ptr = 0;
        for (int s = n; s < TOPK; s++) {
            while (cm[ptr] != 0.0f) ptr++;
            sfill[s] = ptr++;
        }
    }
    __syncthreads();
    for (int s = tid; s < TOPK; s += 1024) {
        bool valid = (s < n);
        float v; int pix;
        if (valid) {
            ull key = sorted[s];
            unsigned ob = ~(unsigned)(key >> 32);
            unsigned bo = (ob & 0x80000000u) ? (ob ^ 0x80000000u) : ~ob;
            v = __uint_as_float(bo);
            pix = (int)((unsigned)key & (HWSZ-1));
        } else {
            v = f_ninf();
            pix = sfill[s];
        }
        int y = pix >> 10, x = pix & (WW-1);
        g_cx[b][s] = valid ? (float)x : 1000000000.0f;
        g_cy[b][s] = valid ? (float)y : 1000000000.0f;
        out[OFF_TOPV + b*TOPK + s] = v;
        out[OFF_CENTERS + (b*TOPK + s)*2 + 0] = (float)y;
        out[OFF_CENTERS + (b*TOPK + s)*2 + 1] = (float)x;
    }
}

// ---------------- K4: streaming softmax/argmax, 4 px/thread (half prob store) ----------------
__global__ void k4_softmax(const float* __restrict__ logits, float* __restrict__ out) {
    const int qp = blockIdx.x * blockDim.x + threadIdx.x;
    const int b = blockIdx.y;
    const float4* base = (const float4*)(logits + (size_t)b * NCLS * HWSZ);
    float m[4] = {f_ninf(), f_ninf(), f_ninf(), f_ninf()};
    int   am[4] = {0, 0, 0, 0};
    float s[4] = {0.f, 0.f, 0.f, 0.f};
    float e[4][10];
    #pragma unroll
    for (int c = 0; c < NCLS; c++) {
        float4 l = __ldg(&base[(size_t)c * (HWSZ/4) + qp]);
        float lv[4] = {l.x, l.y, l.z, l.w};
        #pragma unroll
        for (int k = 0; k < 4; k++) {
            if (lv[k] > m[k]) { m[k] = lv[k]; am[k] = c; }
            float ex = __expf(lv[k]);
            s[k] += ex;
            if (c >= 24) e[k][c - 24] = ex;
        }
    }
    ((float4*)(out + OFF_SEG  + (b << 19)))[qp] =
        make_float4((float)am[0], (float)am[1], (float)am[2], (float)am[3]);
    ((float4*)(out + OFF_INST + (b << 19)))[qp] = make_float4(0.f, 0.f, 0.f, 0.f);
    const int lane = threadIdx.x & 31;
    const unsigned below = (1u << lane) - 1u;
    unsigned mb[4]; int cnt[4];
    #pragma unroll
    for (int k = 0; k < 4; k++) {
        mb[k] = __ballot_sync(0xFFFFFFFFu, am[k] >= 24);
        cnt[k] = __popc(mb[k]);
    }
    int tot = cnt[0] + cnt[1] + cnt[2] + cnt[3];
    int base_i = 0;
    if (lane == 0 && tot) base_i = atomicAdd(&g_tcnt, tot);
    base_i = __shfl_sync(0xFFFFFFFFu, base_i, 0);
    int run = 0;
    #pragma unroll
    for (int k = 0; k < 4; k++) {
        if (am[k] >= 24) {
            int idx = base_i + run + __popc(mb[k] & below);
            float inv = 1.0f / s[k];
            g_tpix[idx] = ((unsigned)b << 19) | (unsigned)(4*qp + k);
            g_tcls[idx] = (unsigned char)am[k];
            #pragma unroll
            for (int j = 0; j < 10; j++) g_tprob[j][idx] = __float2half_rn(e[k][j] * inv);
        }
        run += cnt[k];
    }
}

// ---------------- K5: argmin over centers (f32x2, bit-exact) + counts ----------------
__global__ void k5_argmin(const float* __restrict__ reg, float* __restrict__ out) {
    __shared__ ull sncx2[BATCH][TOPK/2];
    __shared__ ull sncy2[BATCH][TOPK/2];
    __shared__ unsigned int scount[BATCH*TOPK*10];
    const int tid = threadIdx.x;
    for (int i = tid; i < BATCH*(TOPK/2); i += blockDim.x) {
        int b = i / (TOPK/2), k = i % (TOPK/2);
        sncx2[b][k] = pk2(-g_cx[b][2*k], -g_cx[b][2*k + 1]);
        sncy2[b][k] = pk2(-g_cy[b][2*k], -g_cy[b][2*k + 1]);
    }
    for (int i = tid; i < BATCH*TOPK*10; i += blockDim.x) scount[i] = 0;
    __syncthreads();
    const int n = g_tcnt;
    for (int e = blockIdx.x * blockDim.x + tid; e < n; e += gridDim.x * blockDim.x) {
        unsigned gpix = g_tpix[e];
        int b = gpix >> 19;
        int pix = gpix & (HWSZ-1);
        int y = pix >> 10, x = pix & (WW-1);
        float rx = __ldg(&reg[(size_t)b * 2 * HWSZ + pix]);
        float ry = __ldg(&reg[(size_t)(b * 2 + 1) * HWSZ + pix]);
        float px = __fadd_rn((float)(x + 1), -rx);
        float py = __fadd_rn((float)(y + 1), -ry);
        ull px2 = pk2(px, px), py2 = pk2(py, py);
        float best = f_inf(); int bi = 0;
        #pragma unroll 4
        for (int i = 0; i < TOPK/2; i++) {
            ull dx2 = addf2(px2, sncx2[b][i]);
            ull dy2 = addf2(py2, sncy2[b][i]);
            ull d2  = addf2(mulf2(dx2, dx2), mulf2(dy2, dy2));
            float lo, hi; upk2(d2, lo, hi);
            if (lo < best) { best = lo; bi = 2*i; }
            if (hi < best) { best = hi; bi = 2*i + 1; }
        }
        out[OFF_INST + gpix] = (float)(bi + 1);
        g_tinst[e] = bi + 1;
        int cls = g_tcls[e];
        atomicAdd(&scount[(b*TOPK + bi)*10 + (cls - 24)], 1u);
    }
    __syncthreads();
    for (int i = tid; i < BATCH*TOPK*10; i += blockDim.x) {
        unsigned v = scount[i];
        if (v) atomicAdd(&g_counts[i], v);
    }
}

// ---------------- K6: per-instance class/size ----------------
__global__ void k6_cls(float* __restrict__ out) {
    int t = blockIdx.x * blockDim.x + threadIdx.x;
    if (t >= BATCH*TOPK) return;
    unsigned size = 0, cm = 0;
    int ci = 0;
    #pragma unroll
    for (int c = 0; c < 10; c++) {
        unsigned v = g_counts[t*10 + c];
        size += v;
        if (v > cm) { cm = v; ci = c; }
    }
    int cls = (size == 0) ? 0 : (24 + ci);
    g_icls[t] = cls;
    out[OFF_ICLS + t] = (float)cls;
    out[OFF_ISZ  + t] = (float)size;
}

// ---------------- K7: prob sums for selected class ----------------
__global__ void k7_psum() {
    __shared__ int   sicls[BATCH*TOPK];
    __shared__ float sps[BATCH*TOPK];
    const int tid = threadIdx.x;
    for (int i = tid; i < BATCH*TOPK; i += blockDim.x) { sicls[i] = g_icls[i]; sps[i] = 0.0f; }
    __syncthreads();
    const int n = g_tcnt;
    for (int e = blockIdx.x * blockDim.x + tid; e < n; e += gridDim.x * blockDim.x) {
        unsigned gpix = g_tpix[e];
        int b = gpix >> 19;
        int inst = g_tinst[e];
        int bin = b*TOPK + inst - 1;
        int c = sicls[bin];
        float p = __half2float(g_tprob[c - 24][e]);
        atomicAdd(&sps[bin], p);
    }
    __syncthreads();
    for (int i = tid; i < BATCH*TOPK; i += blockDim.x)
        if (sps[i] != 0.0f) atomicAdd(&g_psum[i], sps[i]);
}

// ---------------- K8: inst_seg_prob ----------------
__global__ void k8_final(float* __restrict__ out) {
    int t = blockIdx.x * blockDim.x + threadIdx.x;
    if (t >= BATCH*TOPK) return;
    float size = out[OFF_ISZ + t];
    out[OFF_IPROB + t] = g_psum[t] / fmaxf(size, 1.0f);
}

extern "C" void kernel_launch(void* const* d_in, const int* in_sizes, int n_in,
                              void* d_out, int out_size) {
    const float* logits = (const float*)d_in[0];
    const float* reg    = (const float*)d_in[2];
    float* out = (float*)d_out;

    static cudaStream_t s2 = nullptr;
    static cudaEvent_t ev0 = nullptr, ev2 = nullptr;
    if (s2 == nullptr) {
        cudaStreamCreateWithFlags(&s2, cudaStreamNonBlocking);
        cudaEventCreateWithFlags(&ev0, cudaEventDisableTiming);
        cudaEventCreateWithFlags(&ev2, cudaEventDisableTiming);
    }

    double s = 0.0;
    for (int dy = -5; dy <= 5; dy++)
        for (int dx = -5; dx <= 5; dx++)
            if (dx*dx + dy*dy <= 25) s += sqrt((double)(dx*dx + dy*dy));
    double thr = s / 81.0;
    float negthr = (float)(-thr - 1.0);

    k0_reset<<<1, 512>>>();
    cudaEventRecord(ev0, 0);
    cudaStreamWaitEvent(s2, ev0, 0);

    // branch B (softmax, DRAM-bound) on s2
    k4_softmax<<<dim3(HWSZ/1024, BATCH), 256, 0, s2>>>(logits, out);
    cudaEventRecord(ev2, s2);

    // branch A (vote pipeline, math-bound) on default stream
    k1_vote<<<dim3(WW/64, HH/8, BATCH), dim3(32, 8)>>>(reg);
    k2_nms<<<dim3(WW/64, HH/8, BATCH), dim3(32, 8)>>>(out, negthr);
    k3_topk<<<BATCH, 1024>>>(out);

    // join
    cudaStreamWaitEvent(0, ev2, 0);
    k5_argmin<<<296, 256>>>(reg, out);
    k6_cls<<<1, 512>>>(out);
    k7_psum<<<296, 256>>>();
    k8_final<<<1, 512>>>(out);
}